// round 12
// baseline (speedup 1.0000x reference)
#include <cuda_runtime.h>
#include <math.h>

// ---------------------------------------------------------------------------
// Fully fused kernel, 2 images per block. The circuit factorizes into wire
// pairs {0,1} and {2,3}: U = U_A (x) U_B, and each PauliZ expectation is a
// 9-term bilinear form over (1, cos d, sin d) of two angles.
//
// Per block (two images, 224 threads = 7 warps, regs capped via launch_bounds):
//   - threads t<196 issue 8 x-loads (patch t of image A and image B) first
//   - warp 0 computes the theta-dependent 9-term coefficients (syncwarp only)
//   - ONE __syncthreads, then each thread evaluates BOTH patches into 8 regs
//   - GEMV + reduction in two k-halves (k 0-4, then 5-9): each W float4 is
//     loaded once and feeds both images; only 10 accumulators live at a time
//   - dual log_softmax
// ---------------------------------------------------------------------------

__device__ __forceinline__ void ap1(float* vr, float* vi, int m,
    float g00r, float g00i, float g01r, float g01i,
    float g10r, float g10i, float g11r, float g11i)
{
    #pragma unroll
    for (int z = 0; z < 4; z++) {
        if (z & m) continue;
        int z1 = z | m;
        float ar = vr[z],  ai = vi[z];
        float br = vr[z1], bi = vi[z1];
        vr[z]  = g00r*ar - g00i*ai + g01r*br - g01i*bi;
        vi[z]  = g00r*ai + g00i*ar + g01r*bi + g01i*br;
        vr[z1] = g10r*ar - g10i*ai + g11r*br - g11i*bi;
        vi[z1] = g10r*ai + g10i*ar + g11r*bi + g11i*br;
    }
}

__global__ __launch_bounds__(224, 5)
void fused_kernel(const float* __restrict__ x,
                  const float* __restrict__ cw,
                  const float* __restrict__ theta,
                  const float* __restrict__ W,
                  const float* __restrict__ bvec,
                  float* __restrict__ out)
{
    __shared__ float Ur[2][4][4], Ui[2][4][4];     // [pair][z][col]
    __shared__ float M[2][4][4][2];                // [pair][i][j][q]
    __shared__ float2 scA[9], scB[9];              // 9-term coeffs per pair
    __shared__ float wpart[2][7][10];              // [img][warp][k]
    __shared__ float slog[2][10];
    __shared__ float slse[2];

    int t = threadIdx.x;
    int b = blockIdx.x;                            // images 2b, 2b+1

    // ---- Step 0: issue all x loads immediately (8 LDG.128 in flight) ----
    float4 a0a, a0b, a1a, a1b;                     // image A
    float4 b0a, b0b, b1a, b1b;                     // image B
    if (t < 196) {
        int r  = t / 7;
        int c4 = t % 7;
        size_t off = (2 * r) * 56 + 8 * c4;
        const float* pxA = x + (size_t)(2 * b)     * 3136 + off;
        const float* pxB = x + (size_t)(2 * b + 1) * 3136 + off;
        a0a = *(const float4*)(pxA);
        a0b = *(const float4*)(pxA + 4);
        a1a = *(const float4*)(pxA + 56);
        a1b = *(const float4*)(pxA + 60);
        b0a = *(const float4*)(pxB);
        b0b = *(const float4*)(pxB + 4);
        b1a = *(const float4*)(pxB + 56);
        b1b = *(const float4*)(pxB + 60);
    }
    float w00 = cw[0], w01 = cw[1], w10 = cw[2], w11 = cw[3];

    // ---- Prep: warp 0 only, __syncwarp between stages ----
    if (t < 32) {
        if (t < 8) {
            int pair = t >> 2;
            int col  = t & 3;
            float vr[4] = {0.f, 0.f, 0.f, 0.f};
            float vi[4] = {0.f, 0.f, 0.f, 0.f};
            vr[col] = 1.f;
            if (pair == 0) {
                // Ry(th0) w0, Rx(th1) w1, CNOT(0,1), Rx(th4) w0
                { float c = cosf(0.5f*theta[0]), s = sinf(0.5f*theta[0]);
                  ap1(vr, vi, 2,  c,0.f, -s,0.f,  s,0.f,  c,0.f); }
                { float c = cosf(0.5f*theta[1]), s = sinf(0.5f*theta[1]);
                  ap1(vr, vi, 1,  c,0.f, 0.f,-s, 0.f,-s,  c,0.f); }
                { float tr = vr[2], ti = vi[2];
                  vr[2] = vr[3]; vi[2] = vi[3]; vr[3] = tr; vi[3] = ti; }
                { float c = cosf(0.5f*theta[4]), s = sinf(0.5f*theta[4]);
                  ap1(vr, vi, 2,  c,0.f, 0.f,-s, 0.f,-s,  c,0.f); }
            } else {
                // Rz(th2) w2, Ry(th3) w3, CNOT(2,3), Rz(th5) w3
                { float c = cosf(0.5f*theta[2]), s = sinf(0.5f*theta[2]);
                  ap1(vr, vi, 2,  c,-s, 0.f,0.f, 0.f,0.f,  c,s); }
                { float c = cosf(0.5f*theta[3]), s = sinf(0.5f*theta[3]);
                  ap1(vr, vi, 1,  c,0.f, -s,0.f,  s,0.f,  c,0.f); }
                { float tr = vr[2], ti = vi[2];
                  vr[2] = vr[3]; vi[2] = vi[3]; vr[3] = tr; vi[3] = ti; }
                { float c = cosf(0.5f*theta[5]), s = sinf(0.5f*theta[5]);
                  ap1(vr, vi, 1,  c,-s, 0.f,0.f, 0.f,0.f,  c,s); }
            }
            #pragma unroll
            for (int z = 0; z < 4; z++) { Ur[pair][z][col] = vr[z]; Ui[pair][z][col] = vi[z]; }
        }
        __syncwarp();
        {
            int pair = t >> 4;
            int i = (t >> 2) & 3, j = t & 3;
            float p0 = 0.f, p1 = 0.f;
            #pragma unroll
            for (int z = 0; z < 4; z++) {
                float re = Ur[pair][z][i]*Ur[pair][z][j] + Ui[pair][z][i]*Ui[pair][z][j];
                p0 += (z & 2) ? -re : re;
                p1 += (z & 1) ? -re : re;
            }
            M[pair][i][j][0] = p0;
            M[pair][i][j][1] = p1;
        }
        __syncwarp();
        if (t < 18) {
            int pair = (t >= 9) ? 1 : 0;
            int e = pair ? (t - 9) : t;
            int e0 = e / 3, e1 = e % 3;
            float c0 = 0.f, c1 = 0.f;
            #pragma unroll
            for (int s = 0; s < 4; s++) {
                int i = 0, j = 0; float sg = 1.f;
                { int bsel = s & 1; int iw, jw; float ss;
                  if (e0 == 0)      { iw = bsel; jw = bsel;     ss = 1.f; }
                  else if (e0 == 1) { iw = bsel; jw = bsel;     ss = bsel ? -1.f : 1.f; }
                  else              { iw = bsel; jw = 1 - bsel; ss = 1.f; }
                  i |= iw << 1; j |= jw << 1; sg *= ss; }
                { int bsel = (s >> 1) & 1; int iw, jw; float ss;
                  if (e1 == 0)      { iw = bsel; jw = bsel;     ss = 1.f; }
                  else if (e1 == 1) { iw = bsel; jw = bsel;     ss = bsel ? -1.f : 1.f; }
                  else              { iw = bsel; jw = 1 - bsel; ss = 1.f; }
                  i |= iw; j |= jw; sg *= ss; }
                c0 += sg * M[pair][i][j][0];
                c1 += sg * M[pair][i][j][1];
            }
            float2 v = make_float2(0.25f * c0, 0.25f * c1);
            if (pair == 0) scA[e] = v; else scB[e] = v;
        }
    }

    // ---- Conv + sincos for both images (independent of prep) ----
    float Aa1 = 1.f, Aa2 = 0.f, Ab1 = 1.f, Ab2 = 0.f;
    float Ac1 = 1.f, Ac2 = 0.f, Ad1 = 1.f, Ad2 = 0.f;
    float Ba1 = 1.f, Ba2 = 0.f, Bb1 = 1.f, Bb2 = 0.f;
    float Bc1 = 1.f, Bc2 = 0.f, Bd1 = 1.f, Bd2 = 0.f;
    if (t < 196) {
        float d0 = w00*a0a.x + w01*a0a.y + w10*a1a.x + w11*a1a.y;
        float d1 = w00*a0a.z + w01*a0a.w + w10*a1a.z + w11*a1a.w;
        float d2 = w00*a0b.x + w01*a0b.y + w10*a1b.x + w11*a1b.y;
        float d3 = w00*a0b.z + w01*a0b.w + w10*a1b.z + w11*a1b.w;
        __sincosf(d0, &Aa2, &Aa1);
        __sincosf(d1, &Ab2, &Ab1);
        __sincosf(d2, &Ac2, &Ac1);
        __sincosf(d3, &Ad2, &Ad1);
        float e0 = w00*b0a.x + w01*b0a.y + w10*b1a.x + w11*b1a.y;
        float e1 = w00*b0a.z + w01*b0a.w + w10*b1a.z + w11*b1a.w;
        float e2 = w00*b0b.x + w01*b0b.y + w10*b1b.x + w11*b1b.y;
        float e3 = w00*b0b.z + w01*b0b.w + w10*b1b.z + w11*b1b.w;
        __sincosf(e0, &Ba2, &Ba1);
        __sincosf(e1, &Bb2, &Bb1);
        __sincosf(e2, &Bc2, &Bc1);
        __sincosf(e3, &Bd2, &Bd1);
    }
    __syncthreads();   // coefficients ready

    // ---- Patch eval for both images -> 8 feature registers ----
    float Am0 = 0.f, Am1 = 0.f, Am2 = 0.f, Am3 = 0.f;
    float Bm0 = 0.f, Bm1 = 0.f, Bm2 = 0.f, Bm3 = 0.f;
    if (t < 196) {
        float fAa[3] = {1.f, Aa1, Aa2};
        float fAb[3] = {1.f, Ab1, Ab2};
        float fAc[3] = {1.f, Ac1, Ac2};
        float fAd[3] = {1.f, Ad1, Ad2};
        float fBa[3] = {1.f, Ba1, Ba2};
        float fBb[3] = {1.f, Bb1, Bb2};
        float fBc[3] = {1.f, Bc1, Bc2};
        float fBd[3] = {1.f, Bd1, Bd2};

        int idx = 0;
        #pragma unroll
        for (int e0 = 0; e0 < 3; e0++) {
            #pragma unroll
            for (int e1 = 0; e1 < 3; e1++) {
                float2 kA = scA[idx];
                float2 kB = scB[idx];
                idx++;
                float pAA = fAa[e0] * fAb[e1];
                float pAB = fAc[e0] * fAd[e1];
                float pBA = fBa[e0] * fBb[e1];
                float pBB = fBc[e0] * fBd[e1];
                Am0 = fmaf(kA.x, pAA, Am0);
                Am1 = fmaf(kA.y, pAA, Am1);
                Am2 = fmaf(kB.x, pAB, Am2);
                Am3 = fmaf(kB.y, pAB, Am3);
                Bm0 = fmaf(kA.x, pBA, Bm0);
                Bm1 = fmaf(kA.y, pBA, Bm1);
                Bm2 = fmaf(kB.x, pBB, Bm2);
                Bm3 = fmaf(kB.y, pBB, Bm3);
            }
        }
    }

    // ---- GEMV + reduction in two k-halves (5 outputs x 2 images each) ----
    int lane = t & 31, wid = t >> 5;
    #pragma unroll
    for (int half = 0; half < 2; half++) {
        float aA[5], aB[5];
        #pragma unroll
        for (int kk = 0; kk < 5; kk++) { aA[kk] = 0.f; aB[kk] = 0.f; }
        if (t < 196) {
            #pragma unroll
            for (int kk = 0; kk < 5; kk++) {
                int k = half * 5 + kk;
                float4 w4 = __ldg((const float4*)(W + k * 784 + 4 * t));
                aA[kk] = fmaf(Am0, w4.x, fmaf(Am1, w4.y, fmaf(Am2, w4.z, Am3 * w4.w)));
                aB[kk] = fmaf(Bm0, w4.x, fmaf(Bm1, w4.y, fmaf(Bm2, w4.z, Bm3 * w4.w)));
            }
        }
        #pragma unroll
        for (int kk = 0; kk < 5; kk++) {
            float vA = aA[kk], vB = aB[kk];
            #pragma unroll
            for (int d = 16; d > 0; d >>= 1) {
                vA += __shfl_xor_sync(0xffffffffu, vA, d);
                vB += __shfl_xor_sync(0xffffffffu, vB, d);
            }
            aA[kk] = vA; aB[kk] = vB;
        }
        if (lane == 0) {
            #pragma unroll
            for (int kk = 0; kk < 5; kk++) {
                wpart[0][wid][half * 5 + kk] = aA[kk];
                wpart[1][wid][half * 5 + kk] = aB[kk];
            }
        }
    }
    __syncthreads();

    // ---- Final logits + dual log_softmax (warp 0 only) ----
    if (t < 32) {
        if (t < 20) {
            int im = t / 10, k = t % 10;
            float v = bvec[k];
            #pragma unroll
            for (int w = 0; w < 7; w++) v += wpart[im][w][k];
            slog[im][k] = v;
        }
        __syncwarp();
        if (t < 2) {
            float mx = slog[t][0];
            #pragma unroll
            for (int k = 1; k < 10; k++) mx = fmaxf(mx, slog[t][k]);
            float se = 0.f;
            #pragma unroll
            for (int k = 0; k < 10; k++) se += __expf(slog[t][k] - mx);
            slse[t] = mx + __logf(se);
        }
        __syncwarp();
        if (t < 20) {
            int im = t / 10, k = t % 10;
            out[(size_t)(2 * b + im) * 10 + k] = slog[im][k] - slse[im];
        }
    }
}

// ---------------------------------------------------------------------------

extern "C" void kernel_launch(void* const* d_in, const int* in_sizes, int n_in,
                              void* d_out, int out_size)
{
    const float* x     = (const float*)d_in[0];   // [2048,1,56,56]
    const float* cw    = (const float*)d_in[1];   // [1,1,2,2]
    const float* theta = (const float*)d_in[2];   // [6]
    const float* W     = (const float*)d_in[3];   // [10,784]
    const float* bvec  = (const float*)d_in[4];   // [10]
    float* out = (float*)d_out;                   // [2048,10]

    int B = in_sizes[0] / 3136;                   // 2048

    fused_kernel<<<B / 2, 224>>>(x, cw, theta, W, bvec, out);
}